// round 5
// baseline (speedup 1.0000x reference)
#include <cuda_runtime.h>
#include <cuda_bf16.h>
#include <cstdint>

// Problem constants
#define BB 4096
#define CC 32
#define DD 128
#define RR 8
#define ROWS 128             // M rows per CTA
#define THREADS 512          // 16 warps: 4 m-strips x 4 n-strips

#define BSTR 136             // bf16 row stride for S/W tiles (ldmatrix conflict-free)
#define ASTR 132             // float row stride for a/c/d tiles

// ---- smem layout (byte offsets) ----
#define OFF_SHI 0
#define OFF_SLO (OFF_SHI + 128 * BSTR * 2)
#define OFF_WHI (OFF_SLO + 128 * BSTR * 2)
#define OFF_WLO (OFF_WHI + 128 * BSTR * 2)
#define OFF_A   (OFF_WLO + 128 * BSTR * 2)
#define OFF_C   (OFF_A + CC * ASTR * 4)
#define OFF_Dd  (OFF_C + CC * ASTR * 4)
#define OFF_RS  (OFF_Dd + CC * ASTR * 4)
#define OFF_RD  (OFF_RS + 128 * 4 * 4)
#define SMEM_BYTES (OFF_RD + 128 * 4 * 4)   // 194048 B

__device__ __forceinline__ uint32_t smem_u32(const void* p) {
    uint32_t a;
    asm("{ .reg .u64 t; cvta.to.shared.u64 t, %1; cvt.u32.u64 %0, t; }" : "=r"(a) : "l"(p));
    return a;
}
__device__ __forceinline__ float tanh_approx(float x) {
    float y;
    asm("tanh.approx.f32 %0, %1;" : "=f"(y) : "f"(x));
    return y;
}
__device__ __forceinline__ uint32_t pack_bf2(float x, float y) {
    __nv_bfloat162 h = __floats2bfloat162_rn(x, y);
    return *reinterpret_cast<uint32_t*>(&h);
}
__device__ __forceinline__ float bf_res(float x) {
    __nv_bfloat16 h = __float2bfloat16_rn(x);
    return x - __bfloat162float(h);
}

#define LDSM4(r, addr) \
    asm volatile("ldmatrix.sync.aligned.m8n8.x4.shared.b16 {%0,%1,%2,%3}, [%4];" \
        : "=r"((r)[0]), "=r"((r)[1]), "=r"((r)[2]), "=r"((r)[3]) : "r"(addr))

#define MMA_BF16(c, a, b0, b1) \
    asm volatile("mma.sync.aligned.m16n8k16.row.col.f32.bf16.bf16.f32 " \
        "{%0,%1,%2,%3},{%4,%5,%6,%7},{%8,%9},{%0,%1,%2,%3};" \
        : "+f"((c)[0]), "+f"((c)[1]), "+f"((c)[2]), "+f"((c)[3]) \
        : "r"((a)[0]), "r"((a)[1]), "r"((a)[2]), "r"((a)[3]), "r"(b0), "r"(b1))

__global__ __launch_bounds__(THREADS, 1)
void rotation_mma_kernel(const float* __restrict__ src,
                         const float* __restrict__ dat,
                         const float* __restrict__ Wg,
                         const float* __restrict__ Ag,
                         const float* __restrict__ Cg,
                         const float* __restrict__ Dg,
                         float* __restrict__ out)
{
    extern __shared__ char smem[];
    const uint32_t sb = smem_u32(smem);
    const int tid  = threadIdx.x;
    const int lane = tid & 31;
    const int warp = tid >> 5;
    const int mw   = warp >> 2;          // M32 strip (0..3)
    const int nw   = warp & 3;           // N32 strip (0..3)
    const long g0  = (long)blockIdx.x * ROWS;

    // ---- stage S hi/lo bf16 once: [row][k], stride BSTR ----
    {
        const float4* sg = (const float4*)(src + g0 * DD);
        #pragma unroll
        for (int t = 0; t < 8; t++) {
            int idx4 = tid + t * THREADS;          // 0..4095
            int row  = idx4 >> 5;
            int k4   = idx4 & 31;
            float4 f = __ldg(sg + idx4);
            uint2 hi, lo;
            hi.x = pack_bf2(f.x, f.y);  hi.y = pack_bf2(f.z, f.w);
            lo.x = pack_bf2(bf_res(f.x), bf_res(f.y));
            lo.y = pack_bf2(bf_res(f.z), bf_res(f.w));
            int boff = (row * BSTR + k4 * 4) * 2;
            *(uint2*)(smem + OFF_SHI + boff) = hi;
            *(uint2*)(smem + OFF_SLO + boff) = lo;
        }
    }

    // ---- x resident in fragment layout: rows mw*32+mt*16+q(+8), cols nw*32+2t+8nt(+1) ----
    const int q    = lane >> 2;
    const int colb = nw * 32 + 2 * (lane & 3);
    float x[2][4][4];
    {
        #pragma unroll
        for (int mt = 0; mt < 2; mt++) {
            const float* p0 = dat + (g0 + mw * 32 + mt * 16 + q) * DD + colb;
            const float* p1 = p0 + 8 * DD;
            #pragma unroll
            for (int nt = 0; nt < 4; nt++) {
                float2 f0 = *(const float2*)(p0 + nt * 8);
                float2 f1 = *(const float2*)(p1 + nt * 8);
                x[mt][nt][0] = f0.x; x[mt][nt][1] = f0.y;
                x[mt][nt][2] = f1.x; x[mt][nt][3] = f1.y;
            }
        }
    }

    float* RS = (float*)(smem + OFF_RS);
    float* RD = (float*)(smem + OFF_RD);

    // ldmatrix addresses
    const uint32_t a_row = (uint32_t)(mw * 32 + (lane & 15));
    const uint32_t a_k0  = (uint32_t)((lane >> 4) * 8);
    const uint32_t b_n   = (uint32_t)(nw * 32 + (lane & 7) + ((lane >> 4) << 3));
    const uint32_t b_k0  = (uint32_t)(((lane >> 3) & 1) * 8);

    for (int r = 0; r < RR; r++) {
        __syncthreads();   // previous epilogue done with acd/RS; GEMM done with W

        // ---- stage W[r] hi/lo ----
        {
            const float4* wg = (const float4*)(Wg + (size_t)r * DD * DD);
            #pragma unroll
            for (int t = 0; t < 8; t++) {
                int idx4 = tid + t * THREADS;
                int o  = idx4 >> 5;
                int k4 = idx4 & 31;
                float4 f = __ldg(wg + idx4);
                uint2 hi, lo;
                hi.x = pack_bf2(f.x, f.y);  hi.y = pack_bf2(f.z, f.w);
                lo.x = pack_bf2(bf_res(f.x), bf_res(f.y));
                lo.y = pack_bf2(bf_res(f.z), bf_res(f.w));
                int boff = (o * BSTR + k4 * 4) * 2;
                *(uint2*)(smem + OFF_WHI + boff) = hi;
                *(uint2*)(smem + OFF_WLO + boff) = lo;
            }
        }
        // ---- stage a/c/d[r] ----
        {
            const float4* ag = (const float4*)(Ag + (size_t)r * CC * DD);
            const float4* cg = (const float4*)(Cg + (size_t)r * CC * DD);
            const float4* dg = (const float4*)(Dg + (size_t)r * CC * DD);
            float* As = (float*)(smem + OFF_A);
            float* Cs = (float*)(smem + OFF_C);
            float* Ds = (float*)(smem + OFF_Dd);
            #pragma unroll
            for (int t = 0; t < 2; t++) {
                int idx4 = tid + t * THREADS;       // 0..1023
                int ch = idx4 >> 5;
                int c4 = (idx4 & 31) * 4;
                *(float4*)(As + ch * ASTR + c4) = __ldg(ag + idx4);
                *(float4*)(Cs + ch * ASTR + c4) = __ldg(cg + idx4);
                *(float4*)(Ds + ch * ASTR + c4) = __ldg(dg + idx4);
            }
        }
        __syncthreads();

        // ---- tensor GEMM: warp computes M32 x N32 raw-v tile ----
        float acc[2][4][4];
        #pragma unroll
        for (int mt = 0; mt < 2; mt++)
            #pragma unroll
            for (int nt = 0; nt < 4; nt++)
                #pragma unroll
                for (int j = 0; j < 4; j++) acc[mt][nt][j] = 0.f;

        #pragma unroll
        for (int kt = 0; kt < 8; kt++) {
            uint32_t bh0[4], bl0[4], bh1[4], bl1[4];
            {
                uint32_t boff = (b_n * BSTR + (uint32_t)kt * 16 + b_k0) * 2;
                LDSM4(bh0, sb + OFF_WHI + boff);
                LDSM4(bl0, sb + OFF_WLO + boff);
                LDSM4(bh1, sb + OFF_WHI + boff + 16 * BSTR * 2);
                LDSM4(bl1, sb + OFF_WLO + boff + 16 * BSTR * 2);
            }
            #pragma unroll
            for (int mt = 0; mt < 2; mt++) {
                uint32_t ah[4], al[4];
                uint32_t aoff = ((a_row + (uint32_t)mt * 16) * BSTR + (uint32_t)kt * 16 + a_k0) * 2;
                LDSM4(ah, sb + OFF_SHI + aoff);
                LDSM4(al, sb + OFF_SLO + aoff);
                MMA_BF16(acc[mt][0], ah, bh0[0], bh0[1]);
                MMA_BF16(acc[mt][0], al, bh0[0], bh0[1]);
                MMA_BF16(acc[mt][0], ah, bl0[0], bl0[1]);
                MMA_BF16(acc[mt][1], ah, bh0[2], bh0[3]);
                MMA_BF16(acc[mt][1], al, bh0[2], bh0[3]);
                MMA_BF16(acc[mt][1], ah, bl0[2], bl0[3]);
                MMA_BF16(acc[mt][2], ah, bh1[0], bh1[1]);
                MMA_BF16(acc[mt][2], al, bh1[0], bh1[1]);
                MMA_BF16(acc[mt][2], ah, bl1[0], bl1[1]);
                MMA_BF16(acc[mt][3], ah, bh1[2], bh1[3]);
                MMA_BF16(acc[mt][3], al, bh1[2], bh1[3]);
                MMA_BF16(acc[mt][3], ah, bl1[2], bl1[3]);
            }
        }

        // ---- epilogue: tanh/a/c/d + fused (||v||^2, v.x) partials ----
        const float* As = (const float*)(smem + OFF_A);
        const float* Cs = (const float*)(smem + OFF_C);
        const float* Ds = (const float*)(smem + OFF_Dd);

        float sv[4], dv[4];   // [mt*2 + s]: rows mt*16+q, mt*16+8+q
        #pragma unroll
        for (int mt = 0; mt < 2; mt++) {
            const int ch0 = mt * 16 + q;
            const int base0 = ch0 * ASTR + colb;
            const int base1 = base0 + 8 * ASTR;
            float s0 = 0.f, s1 = 0.f, d0 = 0.f, d1 = 0.f;
            #pragma unroll
            for (int nt = 0; nt < 4; nt++) {
                const int o0 = base0 + nt * 8;
                const int o1 = base1 + nt * 8;
                float2 a0 = *(const float2*)(As + o0);
                float2 c0 = *(const float2*)(Cs + o0);
                float2 e0 = *(const float2*)(Ds + o0);
                float2 a1 = *(const float2*)(As + o1);
                float2 c1 = *(const float2*)(Cs + o1);
                float2 e1 = *(const float2*)(Ds + o1);
                float v;
                v = fmaf(tanh_approx(a0.x * acc[mt][nt][0]), c0.x, e0.x);
                acc[mt][nt][0] = v; s0 = fmaf(v, v, s0); d0 = fmaf(v, x[mt][nt][0], d0);
                v = fmaf(tanh_approx(a0.y * acc[mt][nt][1]), c0.y, e0.y);
                acc[mt][nt][1] = v; s0 = fmaf(v, v, s0); d0 = fmaf(v, x[mt][nt][1], d0);
                v = fmaf(tanh_approx(a1.x * acc[mt][nt][2]), c1.x, e1.x);
                acc[mt][nt][2] = v; s1 = fmaf(v, v, s1); d1 = fmaf(v, x[mt][nt][2], d1);
                v = fmaf(tanh_approx(a1.y * acc[mt][nt][3]), c1.y, e1.y);
                acc[mt][nt][3] = v; s1 = fmaf(v, v, s1); d1 = fmaf(v, x[mt][nt][3], d1);
            }
            sv[mt * 2] = s0; sv[mt * 2 + 1] = s1;
            dv[mt * 2] = d0; dv[mt * 2 + 1] = d1;
        }
        // quad-reduce (lanes sharing a row), 8 independent chains
        #pragma unroll
        for (int off = 1; off <= 2; off <<= 1) {
            #pragma unroll
            for (int j = 0; j < 4; j++) {
                sv[j] += __shfl_xor_sync(0xffffffffu, sv[j], off);
                dv[j] += __shfl_xor_sync(0xffffffffu, dv[j], off);
            }
        }
        if ((lane & 3) == 0) {
            #pragma unroll
            for (int mt = 0; mt < 2; mt++) {
                const int row0 = mw * 32 + mt * 16 + q;
                RS[row0 * 4 + nw] = sv[mt * 2];
                RS[(row0 + 8) * 4 + nw] = sv[mt * 2 + 1];
                RD[row0 * 4 + nw] = dv[mt * 2];
                RD[(row0 + 8) * 4 + nw] = dv[mt * 2 + 1];
            }
        }
        __syncthreads();
        #pragma unroll
        for (int mt = 0; mt < 2; mt++) {
            const int row0 = mw * 32 + mt * 16 + q;
            float4 rs0 = *(const float4*)(RS + row0 * 4);
            float4 rd0 = *(const float4*)(RD + row0 * 4);
            float4 rs1 = *(const float4*)(RS + (row0 + 8) * 4);
            float4 rd1 = *(const float4*)(RD + (row0 + 8) * 4);
            const float st0 = (rs0.x + rs0.y) + (rs0.z + rs0.w);
            const float dt0 = (rd0.x + rd0.y) + (rd0.z + rd0.w);
            const float st1 = (rs1.x + rs1.y) + (rs1.z + rs1.w);
            const float dt1 = (rd1.x + rd1.y) + (rd1.z + rd1.w);
            const float m20 = -2.0f * dt0 / fmaxf(st0, 1e-24f);
            const float m21 = -2.0f * dt1 / fmaxf(st1, 1e-24f);
            #pragma unroll
            for (int nt = 0; nt < 4; nt++) {
                x[mt][nt][0] = fmaf(m20, acc[mt][nt][0], x[mt][nt][0]);
                x[mt][nt][1] = fmaf(m20, acc[mt][nt][1], x[mt][nt][1]);
                x[mt][nt][2] = fmaf(m21, acc[mt][nt][2], x[mt][nt][2]);
                x[mt][nt][3] = fmaf(m21, acc[mt][nt][3], x[mt][nt][3]);
            }
        }
    }

    // ---- write result ----
    #pragma unroll
    for (int mt = 0; mt < 2; mt++) {
        float* p0 = out + (g0 + mw * 32 + mt * 16 + q) * DD + colb;
        float* p1 = p0 + 8 * DD;
        #pragma unroll
        for (int nt = 0; nt < 4; nt++) {
            float2 f0, f1;
            f0.x = x[mt][nt][0]; f0.y = x[mt][nt][1];
            f1.x = x[mt][nt][2]; f1.y = x[mt][nt][3];
            *(float2*)(p0 + nt * 8) = f0;
            *(float2*)(p1 + nt * 8) = f1;
        }
    }
}

extern "C" void kernel_launch(void* const* d_in, const int* in_sizes, int n_in,
                              void* d_out, int out_size)
{
    const float* src = (const float*)d_in[0];   // source [4096,32,128]
    const float* dat = (const float*)d_in[1];   // data   [4096,32,128]
    const float* Wg  = (const float*)d_in[2];   // W      [8,128,128]
    const float* Ag  = (const float*)d_in[3];   // a      [8,32,128]
    const float* Cg  = (const float*)d_in[4];   // c      [8,32,128]
    const float* Dg  = (const float*)d_in[5];   // d      [8,32,128]
    float* out = (float*)d_out;

    cudaFuncSetAttribute(rotation_mma_kernel,
                         cudaFuncAttributeMaxDynamicSharedMemorySize, SMEM_BYTES);

    const int grid = (BB * CC) / ROWS;          // 1024
    rotation_mma_kernel<<<grid, THREADS, SMEM_BYTES>>>(src, dat, Wg, Ag, Cg, Dg, out);
}